// round 3
// baseline (speedup 1.0000x reference)
#include <cuda_runtime.h>
#include <math.h>

// Problem constants: B=2, C=128, H=W=128, outc=128, KS=3, N=9, PAD=1
#define Bn 2
#define Cn 128
#define Hh 128
#define Ww 128
#define OC 128

typedef unsigned long long u64;
typedef unsigned int u32;

// -------- scratch (static device globals; no allocation allowed) --------
__device__ float  g_xt [Bn*Hh*Ww*Cn];     // x transposed to [B,H,W,C]
__device__ float  g_om [Bn*Hh*Ww*27];     // 18 offsets + 9 sigmoid(mask) per pixel
__device__ float4 g_wt4[9*32*128];        // w_conv as [k][c4][o] float4 over c
__device__ float  g_wpm[27*9*128];        // w_p/w_m as [oc27][kh*3+kw][c]

__device__ __forceinline__ u32 smem_u32(const void* p) {
    u32 a;
    asm("{ .reg .u64 t; cvta.to.shared.u64 t, %1; cvt.u32.u64 %0, t; }" : "=r"(a) : "l"(p));
    return a;
}

// ---------------------------------------------------------------
// Kernel 0a: transpose x NCHW -> BHWC
__global__ void k_transpose_x(const float* __restrict__ x) {
    __shared__ float tile[32][33];
    int bxw = blockIdx.x, byc = blockIdx.y, bz = blockIdx.z;
    int b = bz >> 7, h = bz & 127;
    int tx = threadIdx.x, ty = threadIdx.y;
#pragma unroll
    for (int i = 0; i < 4; i++) {
        int c = byc * 32 + ty + i * 8;
        tile[ty + i * 8][tx] = x[((b * Cn + c) * Hh + h) * Ww + bxw * 32 + tx];
    }
    __syncthreads();
#pragma unroll
    for (int i = 0; i < 4; i++) {
        int w = bxw * 32 + ty + i * 8;
        g_xt[((b * Hh + h) * Ww + w) * Cn + byc * 32 + tx] = tile[tx][ty + i * 8];
    }
}

// ---------------------------------------------------------------
// Kernel 0b: weight re-layouts (tiny)
__global__ void k_transpose_w(const float* __restrict__ w_conv,
                              const float* __restrict__ w_p,
                              const float* __restrict__ w_m) {
    int t = blockIdx.x * blockDim.x + threadIdx.x;
    if (t < 9 * 32 * 128 * 4) {
        int j  = t & 3;
        int o  = (t >> 2) & 127;
        int c4 = (t >> 9) & 31;
        int k  = t >> 14;
        int c  = c4 * 4 + j;
        int di = k / 3, dj = k - di * 3;
        ((float*)g_wt4)[t] = w_conv[((o * Cn + c) * 3 + di) * 3 + dj];
    } else {
        int t2 = t - 9 * 32 * 128 * 4;
        if (t2 < 27 * 9 * 128) {
            int c  = t2 & 127;
            int idx = t2 >> 7;
            int t9 = idx % 9;
            int oc = idx / 9;
            int kh = t9 / 3, kw = t9 - kh * 3;
            float val;
            if (oc < 18) val = w_p[((oc * Cn + c) * 3 + kh) * 3 + kw];
            else         val = w_m[(((oc - 18) * Cn + c) * 3 + kh) * 3 + kw];
            g_wpm[t2] = val;
        }
    }
}

// ---------------------------------------------------------------
// Kernel A: fused offset(18) + mask(9) 3x3 conv, pad 1. FFMA2 inner loop.
__global__ void k_convA(const float* __restrict__ b_p, const float* __restrict__ b_m) {
    extern __shared__ float smem[];
    float* xs = smem;           // 11664 floats
    float* ws = smem + 11664;   // 7776 floats
    u32 xsb = smem_u32(xs);
    u32 wsb = smem_u32(ws);
    int b  = blockIdx.z;
    int h0 = blockIdx.y * 16, w0 = blockIdx.x * 16;
    int tid = threadIdx.x;
    int px = tid & 15, py = tid >> 4;

    u64 acc2[27];
#pragma unroll
    for (int i = 0; i < 27; i++) acc2[i] = 0ull;

    for (int cc = 0; cc < Cn; cc += 32) {
        for (int e = tid; e < 18 * 18 * 32; e += 256) {
            int c   = e & 31;
            int col = (e >> 5) % 18;
            int row = e / (18 * 32);
            int gh = h0 - 1 + row, gw = w0 - 1 + col;
            float val = 0.f;
            if (gh >= 0 && gh < Hh && gw >= 0 && gw < Ww)
                val = g_xt[((b * Hh + gh) * Ww + gw) * Cn + cc + c];
            xs[(row * 18 + col) * 36 + c] = val;
        }
        for (int e = tid; e < 27 * 9 * 32; e += 256)
            ws[e] = g_wpm[(e >> 5) * 128 + cc + (e & 31)];
        __syncthreads();

#pragma unroll 1
        for (int t9 = 0; t9 < 9; t9++) {
            int kh = t9 / 3, kw = t9 - kh * 3;
            u32 xaddr = xsb + (((py + kh) * 18 + (px + kw)) * 36) * 4;
#pragma unroll 1
            for (int c4 = 0; c4 < 8; c4++) {
                u64 x01, x23;
                asm("ld.shared.v2.u64 {%0,%1}, [%2];"
                    : "=l"(x01), "=l"(x23) : "r"(xaddr + c4 * 16));
#pragma unroll
                for (int oc = 0; oc < 27; oc++) {
                    u64 w01, w23;
                    asm("ld.shared.v2.u64 {%0,%1}, [%2];"
                        : "=l"(w01), "=l"(w23)
                        : "r"(wsb + ((oc * 9 + t9) * 32 + c4 * 4) * 4));
                    asm("fma.rn.f32x2 %0, %1, %2, %0;" : "+l"(acc2[oc]) : "l"(x01), "l"(w01));
                    asm("fma.rn.f32x2 %0, %1, %2, %0;" : "+l"(acc2[oc]) : "l"(x23), "l"(w23));
                }
            }
        }
        __syncthreads();
    }

    float acc[27];
#pragma unroll
    for (int i = 0; i < 27; i++) {
        float lo, hi;
        asm("mov.b64 {%0,%1}, %2;" : "=f"(lo), "=f"(hi) : "l"(acc2[i]));
        acc[i] = lo + hi;
    }

    int h = h0 + py, w = w0 + px;
    float* dst = &g_om[((b * Hh + h) * Ww + w) * 27];
#pragma unroll
    for (int ch = 0; ch < 18; ch++) dst[ch] = acc[ch] + b_p[ch];
#pragma unroll
    for (int n = 0; n < 9; n++) {
        float t = acc[18 + n] + b_m[n];
        dst[18 + n] = 1.f / (1.f + expf(-t));
    }
}

// ---------------------------------------------------------------
// Gather one conv-tap k for a 32-pixel tile into smem buf[32][128].
// Each warp handles 2 pixels; lanes cover 128 channels as float4.
__device__ __forceinline__ void gather_tap(int b, int k, int oh0, int ow0,
                                           int lane, int wi, float* buf) {
    const float4* xt4 = (const float4*)g_xt;
    int di = k / 3, dj = k - di * 3;
    int dh = (di == 0) ? -1 : 0;
    int iI = (di == 0) ? 2 : (di == 1 ? 0 : 1);
    int dw = (dj == 0) ? -1 : 0;
    int jJ = (dj == 0) ? 2 : (dj == 1 ? 0 : 1);
    int n = iI * 3 + jJ;
#pragma unroll
    for (int s = 0; s < 2; s++) {
        int p = wi * 2 + s;
        int ly = p >> 2, lx = p & 3;
        int h = oh0 + ly + dh, w = ow0 + lx + dw;
        float4* vd4 = (float4*)&buf[p * 128];
        if (h < 0 || w < 0) { vd4[lane] = make_float4(0.f, 0.f, 0.f, 0.f); continue; }
        const float* om = &g_om[((b * Hh + h) * Ww + w) * 27];
        float offx = om[n], offy = om[9 + n], mval = om[18 + n];
        float p_x = offx + (float)(iI - 1) + (float)(h + 1);
        float p_y = offy + (float)(jJ - 1) + (float)(w + 1);
        float flx = floorf(p_x), fly = floorf(p_y);
        float ltx = fminf(fmaxf(flx, 0.f), 129.f);
        float lty = fminf(fmaxf(fly, 0.f), 129.f);
        float rbx = fminf(fmaxf(flx + 1.f, 0.f), 129.f);
        float rby = fminf(fmaxf(fly + 1.f, 0.f), 129.f);
        float cpx = fminf(fmaxf(p_x, 0.f), 129.f);
        float cpy = fminf(fmaxf(p_y, 0.f), 129.f);
        float ax  = 1.f + (ltx - cpx);
        float bx_ = 1.f - (rbx - cpx);
        float ay  = 1.f + (lty - cpy);
        float by_ = 1.f - (rby - cpy);
        float wq[4] = { ax * ay * mval, bx_ * by_ * mval, ax * by_ * mval, bx_ * ay * mval };
        float qxf[4] = { ltx, rbx, ltx, rbx };
        float qyf[4] = { lty, rby, rby, lty };
        int base4[4];
#pragma unroll
        for (int j = 0; j < 4; j++) {
            int ix = (int)qxf[j], iy = (int)qyf[j];
            bool valid = (ix >= 1 && ix <= Hh && iy >= 1 && iy <= Ww);
            base4[j] = valid ? (((b * Hh + ix - 1) * Ww + iy - 1) * 32) : 0;
            if (!valid) wq[j] = 0.f;
        }
        float4 a0 = xt4[base4[0] + lane];
        float4 a1 = xt4[base4[1] + lane];
        float4 a2 = xt4[base4[2] + lane];
        float4 a3 = xt4[base4[3] + lane];
        float4 sv;
        sv.x = wq[0]*a0.x + wq[1]*a1.x + wq[2]*a2.x + wq[3]*a3.x;
        sv.y = wq[0]*a0.y + wq[1]*a1.y + wq[2]*a2.y + wq[3]*a3.y;
        sv.z = wq[0]*a0.z + wq[1]*a1.z + wq[2]*a2.z + wq[3]*a3.z;
        sv.w = wq[0]*a0.w + wq[1]*a1.w + wq[2]*a2.w + wq[3]*a3.w;
        vd4[lane] = sv;
    }
}

// ---------------------------------------------------------------
// Kernel B: per-tap double-buffered deformable gather + FFMA2 GEMM.
// Block 512 thr, tile 8x4 = 32 output pixels, all 128 out channels.
__global__ void __launch_bounds__(512, 2) k_deform(float* __restrict__ out) {
    __shared__ float vbuf[2][32 * 128];   // 2 x 16 KB
    int b   = blockIdx.z;
    int oh0 = blockIdx.y * 8, ow0 = blockIdx.x * 4;
    int tid  = threadIdx.x;
    int lane = tid & 31, wi = tid >> 5;
    int o  = tid & 127;
    int pg = tid >> 7;            // 0..3 -> pixels [pg*8, pg*8+8)

    u32 vb0 = smem_u32(vbuf[0]);

    u64 accA[8], accB[8];
#pragma unroll
    for (int q = 0; q < 8; q++) { accA[q] = 0ull; accB[q] = 0ull; }

    gather_tap(b, 0, oh0, ow0, lane, wi, vbuf[0]);
    __syncthreads();

#pragma unroll 1
    for (int k = 0; k < 9; k++) {
        if (k < 8) gather_tap(b, k + 1, oh0, ow0, lane, wi, vbuf[(k + 1) & 1]);

        const float4* wk = &g_wt4[k * 32 * 128 + o];
        u32 va = vb0 + (u32)((k & 1) * 16384) + (u32)(pg * 8) * 512u;
#pragma unroll 1
        for (int c4 = 0; c4 < 32; c4++) {
            u64 w01, w23;
            asm("ld.global.nc.v2.u64 {%0,%1}, [%2];"
                : "=l"(w01), "=l"(w23) : "l"(wk + c4 * 128));
            u32 vc = va + (u32)c4 * 16u;
#pragma unroll
            for (int q = 0; q < 8; q++) {
                u64 v01, v23;
                asm("ld.shared.v2.u64 {%0,%1}, [%2];"
                    : "=l"(v01), "=l"(v23) : "r"(vc + (u32)q * 512u));
                asm("fma.rn.f32x2 %0, %1, %2, %0;" : "+l"(accA[q]) : "l"(v01), "l"(w01));
                asm("fma.rn.f32x2 %0, %1, %2, %0;" : "+l"(accB[q]) : "l"(v23), "l"(w23));
            }
        }
        __syncthreads();
    }

    float acc[8];
#pragma unroll
    for (int q = 0; q < 8; q++) {
        float la, ha, lb, hb;
        asm("mov.b64 {%0,%1}, %2;" : "=f"(la), "=f"(ha) : "l"(accA[q]));
        asm("mov.b64 {%0,%1}, %2;" : "=f"(lb), "=f"(hb) : "l"(accB[q]));
        acc[q] = (la + ha) + (lb + hb);
    }

    // q0..3 -> row oh0+pg*2 cols ow0..+3 ; q4..7 -> row oh0+pg*2+1
    int ohA = oh0 + pg * 2;
    float4 r0 = make_float4(acc[0], acc[1], acc[2], acc[3]);
    float4 r1 = make_float4(acc[4], acc[5], acc[6], acc[7]);
    *(float4*)&out[((b * OC + o) * Hh + ohA)     * Ww + ow0] = r0;
    *(float4*)&out[((b * OC + o) * Hh + ohA + 1) * Ww + ow0] = r1;
}

// ---------------------------------------------------------------
extern "C" void kernel_launch(void* const* d_in, const int* in_sizes, int n_in,
                              void* d_out, int out_size) {
    const float* x      = (const float*)d_in[0];
    const float* w_p    = (const float*)d_in[1];
    const float* b_p    = (const float*)d_in[2];
    const float* w_m    = (const float*)d_in[3];
    const float* b_m    = (const float*)d_in[4];
    const float* w_conv = (const float*)d_in[5];
    float* out = (float*)d_out;

    cudaFuncSetAttribute(k_convA, cudaFuncAttributeMaxDynamicSharedMemorySize, (11664 + 7776) * 4);

    k_transpose_x<<<dim3(4, 4, Bn * Hh), dim3(32, 8)>>>(x);

    int wthreads = 9 * 32 * 128 * 4 + 27 * 9 * 128;
    k_transpose_w<<<(wthreads + 255) / 256, 256>>>(w_conv, w_p, w_m);

    k_convA<<<dim3(8, 8, Bn), 256, (11664 + 7776) * 4>>>(b_p, b_m);

    k_deform<<<dim3(32, 16, Bn), 512>>>(out);
}

// round 4
// speedup vs baseline: 1.0670x; 1.0670x over previous
#include <cuda_runtime.h>
#include <math.h>

// Problem constants: B=2, C=128, H=W=128, outc=128, KS=3, N=9, PAD=1
#define Bn 2
#define Cn 128
#define Hh 128
#define Ww 128
#define OC 128

typedef unsigned long long u64;
typedef unsigned int u32;

// -------- scratch (static device globals; no allocation allowed) --------
__device__ float  g_xt [Bn*Hh*Ww*Cn];     // x transposed to [B,H,W,C]
__device__ float  g_om [Bn*Hh*Ww*27];     // 18 offsets + 9 sigmoid(mask) per pixel
__device__ float4 g_wt4[9*32*128];        // w_conv as [k][c4][o] float4 over c
__device__ float  g_wpm[27*9*128];        // w_p/w_m as [oc27][kh*3+kw][c]

__device__ __forceinline__ u32 smem_u32(const void* p) {
    u32 a;
    asm("{ .reg .u64 t; cvta.to.shared.u64 t, %1; cvt.u32.u64 %0, t; }" : "=r"(a) : "l"(p));
    return a;
}

// ---------------------------------------------------------------
// Kernel 0a: transpose x NCHW -> BHWC
__global__ void k_transpose_x(const float* __restrict__ x) {
    __shared__ float tile[32][33];
    int bxw = blockIdx.x, byc = blockIdx.y, bz = blockIdx.z;
    int b = bz >> 7, h = bz & 127;
    int tx = threadIdx.x, ty = threadIdx.y;
#pragma unroll
    for (int i = 0; i < 4; i++) {
        int c = byc * 32 + ty + i * 8;
        tile[ty + i * 8][tx] = x[((b * Cn + c) * Hh + h) * Ww + bxw * 32 + tx];
    }
    __syncthreads();
#pragma unroll
    for (int i = 0; i < 4; i++) {
        int w = bxw * 32 + ty + i * 8;
        g_xt[((b * Hh + h) * Ww + w) * Cn + byc * 32 + tx] = tile[tx][ty + i * 8];
    }
}

// ---------------------------------------------------------------
// Kernel 0b: weight re-layouts (tiny)
__global__ void k_transpose_w(const float* __restrict__ w_conv,
                              const float* __restrict__ w_p,
                              const float* __restrict__ w_m) {
    int t = blockIdx.x * blockDim.x + threadIdx.x;
    if (t < 9 * 32 * 128 * 4) {
        int j  = t & 3;
        int o  = (t >> 2) & 127;
        int c4 = (t >> 9) & 31;
        int k  = t >> 14;
        int c  = c4 * 4 + j;
        int di = k / 3, dj = k - di * 3;
        ((float*)g_wt4)[t] = w_conv[((o * Cn + c) * 3 + di) * 3 + dj];
    } else {
        int t2 = t - 9 * 32 * 128 * 4;
        if (t2 < 27 * 9 * 128) {
            int c  = t2 & 127;
            int idx = t2 >> 7;
            int t9 = idx % 9;
            int oc = idx / 9;
            int kh = t9 / 3, kw = t9 - kh * 3;
            float val;
            if (oc < 18) val = w_p[((oc * Cn + c) * 3 + kh) * 3 + kw];
            else         val = w_m[(((oc - 18) * Cn + c) * 3 + kh) * 3 + kw];
            g_wpm[t2] = val;
        }
    }
}

// ---------------------------------------------------------------
// Kernel A: fused offset(18) + mask(9) 3x3 conv, pad 1. FFMA2 inner loop.
__global__ void k_convA(const float* __restrict__ b_p, const float* __restrict__ b_m) {
    extern __shared__ float smem[];
    float* xs = smem;           // 11664 floats
    float* ws = smem + 11664;   // 7776 floats
    u32 xsb = smem_u32(xs);
    u32 wsb = smem_u32(ws);
    int b  = blockIdx.z;
    int h0 = blockIdx.y * 16, w0 = blockIdx.x * 16;
    int tid = threadIdx.x;
    int px = tid & 15, py = tid >> 4;

    u64 acc2[27];
#pragma unroll
    for (int i = 0; i < 27; i++) acc2[i] = 0ull;

    for (int cc = 0; cc < Cn; cc += 32) {
        for (int e = tid; e < 18 * 18 * 32; e += 256) {
            int c   = e & 31;
            int col = (e >> 5) % 18;
            int row = e / (18 * 32);
            int gh = h0 - 1 + row, gw = w0 - 1 + col;
            float val = 0.f;
            if (gh >= 0 && gh < Hh && gw >= 0 && gw < Ww)
                val = g_xt[((b * Hh + gh) * Ww + gw) * Cn + cc + c];
            xs[(row * 18 + col) * 36 + c] = val;
        }
        for (int e = tid; e < 27 * 9 * 32; e += 256)
            ws[e] = g_wpm[(e >> 5) * 128 + cc + (e & 31)];
        __syncthreads();

#pragma unroll 1
        for (int t9 = 0; t9 < 9; t9++) {
            int kh = t9 / 3, kw = t9 - kh * 3;
            u32 xaddr = xsb + (((py + kh) * 18 + (px + kw)) * 36) * 4;
#pragma unroll 1
            for (int c4 = 0; c4 < 8; c4++) {
                u64 x01, x23;
                asm("ld.shared.v2.u64 {%0,%1}, [%2];"
                    : "=l"(x01), "=l"(x23) : "r"(xaddr + c4 * 16));
#pragma unroll
                for (int oc = 0; oc < 27; oc++) {
                    u64 w01, w23;
                    asm("ld.shared.v2.u64 {%0,%1}, [%2];"
                        : "=l"(w01), "=l"(w23)
                        : "r"(wsb + ((oc * 9 + t9) * 32 + c4 * 4) * 4));
                    asm("fma.rn.f32x2 %0, %1, %2, %0;" : "+l"(acc2[oc]) : "l"(x01), "l"(w01));
                    asm("fma.rn.f32x2 %0, %1, %2, %0;" : "+l"(acc2[oc]) : "l"(x23), "l"(w23));
                }
            }
        }
        __syncthreads();
    }

    float acc[27];
#pragma unroll
    for (int i = 0; i < 27; i++) {
        float lo, hi;
        asm("mov.b64 {%0,%1}, %2;" : "=f"(lo), "=f"(hi) : "l"(acc2[i]));
        acc[i] = lo + hi;
    }

    int h = h0 + py, w = w0 + px;
    float* dst = &g_om[((b * Hh + h) * Ww + w) * 27];
#pragma unroll
    for (int ch = 0; ch < 18; ch++) dst[ch] = acc[ch] + b_p[ch];
#pragma unroll
    for (int n = 0; n < 9; n++) {
        float t = acc[18 + n] + b_m[n];
        dst[18 + n] = 1.f / (1.f + expf(-t));
    }
}

// ---------------------------------------------------------------
// Gather one conv-tap k for a 32-pixel tile into smem buf[32][128].
// Each warp handles 2 pixels; lanes cover 128 channels as float4.
__device__ __forceinline__ void gather_tap(int b, int k, int oh0, int ow0,
                                           int lane, int wi, float* buf) {
    const float4* xt4 = (const float4*)g_xt;
    int di = k / 3, dj = k - di * 3;
    int dh = (di == 0) ? -1 : 0;
    int iI = (di == 0) ? 2 : (di == 1 ? 0 : 1);
    int dw = (dj == 0) ? -1 : 0;
    int jJ = (dj == 0) ? 2 : (dj == 1 ? 0 : 1);
    int n = iI * 3 + jJ;
#pragma unroll
    for (int s = 0; s < 2; s++) {
        int p = wi * 2 + s;
        int ly = p >> 2, lx = p & 3;
        int h = oh0 + ly + dh, w = ow0 + lx + dw;
        float4* vd4 = (float4*)&buf[p * 128];
        if (h < 0 || w < 0) { vd4[lane] = make_float4(0.f, 0.f, 0.f, 0.f); continue; }
        const float* om = &g_om[((b * Hh + h) * Ww + w) * 27];
        float offx = om[n], offy = om[9 + n], mval = om[18 + n];
        float p_x = offx + (float)(iI - 1) + (float)(h + 1);
        float p_y = offy + (float)(jJ - 1) + (float)(w + 1);
        float flx = floorf(p_x), fly = floorf(p_y);
        float ltx = fminf(fmaxf(flx, 0.f), 129.f);
        float lty = fminf(fmaxf(fly, 0.f), 129.f);
        float rbx = fminf(fmaxf(flx + 1.f, 0.f), 129.f);
        float rby = fminf(fmaxf(fly + 1.f, 0.f), 129.f);
        float cpx = fminf(fmaxf(p_x, 0.f), 129.f);
        float cpy = fminf(fmaxf(p_y, 0.f), 129.f);
        float ax  = 1.f + (ltx - cpx);
        float bx_ = 1.f - (rbx - cpx);
        float ay  = 1.f + (lty - cpy);
        float by_ = 1.f - (rby - cpy);
        float wq[4] = { ax * ay * mval, bx_ * by_ * mval, ax * by_ * mval, bx_ * ay * mval };
        float qxf[4] = { ltx, rbx, ltx, rbx };
        float qyf[4] = { lty, rby, rby, lty };
        int base4[4];
#pragma unroll
        for (int j = 0; j < 4; j++) {
            int ix = (int)qxf[j], iy = (int)qyf[j];
            bool valid = (ix >= 1 && ix <= Hh && iy >= 1 && iy <= Ww);
            base4[j] = valid ? (((b * Hh + ix - 1) * Ww + iy - 1) * 32) : 0;
            if (!valid) wq[j] = 0.f;
        }
        float4 a0 = xt4[base4[0] + lane];
        float4 a1 = xt4[base4[1] + lane];
        float4 a2 = xt4[base4[2] + lane];
        float4 a3 = xt4[base4[3] + lane];
        float4 sv;
        sv.x = wq[0]*a0.x + wq[1]*a1.x + wq[2]*a2.x + wq[3]*a3.x;
        sv.y = wq[0]*a0.y + wq[1]*a1.y + wq[2]*a2.y + wq[3]*a3.y;
        sv.z = wq[0]*a0.z + wq[1]*a1.z + wq[2]*a2.z + wq[3]*a3.z;
        sv.w = wq[0]*a0.w + wq[1]*a1.w + wq[2]*a2.w + wq[3]*a3.w;
        vd4[lane] = sv;
    }
}

// ---------------------------------------------------------------
// Kernel B: deformable gather + FFMA2 GEMM with cp.async weight staging.
// Block 512 thr, tile 8x4 = 32 output pixels, all 128 out channels.
// smem: vbuf[2][32*128] (32KB) + wbuf[2][8*128 float4] (32KB) = 64KB dynamic.
__global__ void __launch_bounds__(512, 2) k_deform(float* __restrict__ out) {
    extern __shared__ float sm[];
    float*  vbuf = sm;                       // 8192 floats
    float4* wbuf = (float4*)(sm + 8192);     // 2048 float4
    u32 vb0 = smem_u32(vbuf);
    u32 wb0 = smem_u32(wbuf);

    int b   = blockIdx.z;
    int oh0 = blockIdx.y * 8, ow0 = blockIdx.x * 4;
    int tid  = threadIdx.x;
    int lane = tid & 31, wi = tid >> 5;
    int o  = tid & 127;
    int pg = tid >> 7;            // 0..3

    // initial stage: weights (k=0, chunk 0) + gather tap 0
    {
        const float4* srcw = &g_wt4[0];
        wbuf[tid]       = srcw[tid];
        wbuf[tid + 512] = srcw[tid + 512];
    }
    gather_tap(b, 0, oh0, ow0, lane, wi, vbuf);
    __syncthreads();

    u64 accA[8], accB[8];
#pragma unroll
    for (int q = 0; q < 8; q++) { accA[q] = 0ull; accB[q] = 0ull; }

    int sbuf = 0;
#pragma unroll 1
    for (int k = 0; k < 9; k++) {
#pragma unroll 1
        for (int cc = 0; cc < 4; cc++) {
            // async-stage next weight chunk into wbuf[sbuf^1]
            int nk = k, ncc = cc + 1;
            if (ncc == 4) { ncc = 0; nk++; }
            if (nk < 9) {
                const float4* srcw = &g_wt4[(nk * 32 + ncc * 8) * 128];
                u32 dstw = wb0 + (u32)((sbuf ^ 1) * 16384) + (u32)tid * 16u;
                asm volatile("cp.async.cg.shared.global [%0], [%1], 16;"
                             :: "r"(dstw), "l"(srcw + tid));
                asm volatile("cp.async.cg.shared.global [%0], [%1], 16;"
                             :: "r"(dstw + 8192u), "l"(srcw + tid + 512));
                asm volatile("cp.async.commit_group;");
            }
            // gather next tap (once per k, placed after chunk-0 staging)
            if (cc == 1 && k < 8)
                gather_tap(b, k + 1, oh0, ow0, lane, wi, vbuf + ((k + 1) & 1) * 4096);

            // GEMM over this chunk's 8 c4 (global c4 = cc*8 + c4l)
            u32 wa = wb0 + (u32)(sbuf * 16384) + (u32)o * 16u;
            u32 va = vb0 + (u32)((k & 1) * 16384) + (u32)pg * 4096u + (u32)cc * 128u;
#pragma unroll
            for (int c4l = 0; c4l < 8; c4l++) {
                u64 w01, w23;
                asm("ld.shared.v2.u64 {%0,%1}, [%2];"
                    : "=l"(w01), "=l"(w23) : "r"(wa + (u32)c4l * 2048u));
                u32 vc = va + (u32)c4l * 16u;
#pragma unroll
                for (int q = 0; q < 8; q++) {
                    u64 v01, v23;
                    asm("ld.shared.v2.u64 {%0,%1}, [%2];"
                        : "=l"(v01), "=l"(v23) : "r"(vc + (u32)q * 512u));
                    asm("fma.rn.f32x2 %0, %1, %2, %0;" : "+l"(accA[q]) : "l"(v01), "l"(w01));
                    asm("fma.rn.f32x2 %0, %1, %2, %0;" : "+l"(accB[q]) : "l"(v23), "l"(w23));
                }
            }
            asm volatile("cp.async.wait_group 0;");
            __syncthreads();
            sbuf ^= 1;
        }
    }

    float acc[8];
#pragma unroll
    for (int q = 0; q < 8; q++) {
        float la, ha, lb, hb;
        asm("mov.b64 {%0,%1}, %2;" : "=f"(la), "=f"(ha) : "l"(accA[q]));
        asm("mov.b64 {%0,%1}, %2;" : "=f"(lb), "=f"(hb) : "l"(accB[q]));
        acc[q] = (la + ha) + (lb + hb);
    }

    int ohA = oh0 + pg * 2;
    float4 r0 = make_float4(acc[0], acc[1], acc[2], acc[3]);
    float4 r1 = make_float4(acc[4], acc[5], acc[6], acc[7]);
    *(float4*)&out[((b * OC + o) * Hh + ohA)     * Ww + ow0] = r0;
    *(float4*)&out[((b * OC + o) * Hh + ohA + 1) * Ww + ow0] = r1;
}

// ---------------------------------------------------------------
extern "C" void kernel_launch(void* const* d_in, const int* in_sizes, int n_in,
                              void* d_out, int out_size) {
    const float* x      = (const float*)d_in[0];
    const float* w_p    = (const float*)d_in[1];
    const float* b_p    = (const float*)d_in[2];
    const float* w_m    = (const float*)d_in[3];
    const float* b_m    = (const float*)d_in[4];
    const float* w_conv = (const float*)d_in[5];
    float* out = (float*)d_out;

    cudaFuncSetAttribute(k_convA,  cudaFuncAttributeMaxDynamicSharedMemorySize, (11664 + 7776) * 4);
    cudaFuncSetAttribute(k_deform, cudaFuncAttributeMaxDynamicSharedMemorySize, 65536);

    k_transpose_x<<<dim3(4, 4, Bn * Hh), dim3(32, 8)>>>(x);

    int wthreads = 9 * 32 * 128 * 4 + 27 * 9 * 128;
    k_transpose_w<<<(wthreads + 255) / 256, 256>>>(w_conv, w_p, w_m);

    k_convA<<<dim3(8, 8, Bn), 256, (11664 + 7776) * 4>>>(b_p, b_m);

    k_deform<<<dim3(32, 16, Bn), 512, 65536>>>(out);
}

// round 6
// speedup vs baseline: 2.2665x; 2.1241x over previous
#include <cuda_runtime.h>
#include <cuda_bf16.h>
#include <math.h>

// Problem constants: B=2, C=128, H=W=128, outc=128, KS=3, N=9, PAD=1
#define Bn 2
#define Cn 128
#define Hh 128
#define Ww 128
#define OC 128

typedef unsigned long long u64;
typedef unsigned int u32;

// -------- scratch (static device globals; no allocation allowed) --------
__device__ float g_xt [Bn*Hh*Ww*Cn];                 // x as [B,H,W,C]
__device__ float g_om [Bn*Hh*Ww*27];                 // 18 offsets + 9 sigmoid(mask)
__device__ float g_wpm[27*9*128];                    // w_p/w_m for convA
// w_conv per tap: hi tile (128 o-rows x 136 cols bf16) then lo tile; exact smem image
__device__ __align__(16) unsigned char g_wb2[9*2*34816];

#define A_STRIDE_B 272              // 136 bf16 per row
#define A_HI_BYTES 17408            // 64 rows
#define B_TILE_BYTES 34816          // 128 rows
#define SMEM_B_OFF 34816            // A hi (17408) + A lo (17408)
#define SMEM_TOTAL (34816 + 69632)  // 104448

__device__ __forceinline__ u32 smem_u32(const void* p) {
    u32 a;
    asm("{ .reg .u64 t; cvta.to.shared.u64 t, %1; cvt.u32.u64 %0, t; }" : "=r"(a) : "l"(p));
    return a;
}

// ---------------------------------------------------------------
// Kernel 0a: transpose x NCHW -> BHWC
__global__ void k_transpose_x(const float* __restrict__ x) {
    __shared__ float tile[32][33];
    int bxw = blockIdx.x, byc = blockIdx.y, bz = blockIdx.z;
    int b = bz >> 7, h = bz & 127;
    int tx = threadIdx.x, ty = threadIdx.y;
#pragma unroll
    for (int i = 0; i < 4; i++) {
        int c = byc * 32 + ty + i * 8;
        tile[ty + i * 8][tx] = x[((b * Cn + c) * Hh + h) * Ww + bxw * 32 + tx];
    }
    __syncthreads();
#pragma unroll
    for (int i = 0; i < 4; i++) {
        int w = bxw * 32 + ty + i * 8;
        g_xt[((b * Hh + h) * Ww + w) * Cn + byc * 32 + tx] = tile[tx][ty + i * 8];
    }
}

// ---------------------------------------------------------------
// Kernel 0b: weight re-layouts.
// Range 1: w_conv -> g_wb2[k]: hi/lo bf16 tiles, [o][c] rows with stride 136.
// Range 2: w_p/w_m -> g_wpm for convA.
__global__ void k_transpose_w(const float* __restrict__ w_conv,
                              const float* __restrict__ w_p,
                              const float* __restrict__ w_m) {
    int t = blockIdx.x * blockDim.x + threadIdx.x;
    if (t < 9 * 128 * 128) {
        int c = t & 127;
        int o = (t >> 7) & 127;
        int k = t >> 14;
        int di = k / 3, dj = k - di * 3;
        float val = w_conv[((o * Cn + c) * 3 + di) * 3 + dj];
        __nv_bfloat16 hi = __float2bfloat16(val);
        __nv_bfloat16 lo = __float2bfloat16(val - __bfloat162float(hi));
        unsigned char* base = g_wb2 + k * (2 * B_TILE_BYTES);
        *(__nv_bfloat16*)(base + o * A_STRIDE_B + c * 2) = hi;
        *(__nv_bfloat16*)(base + B_TILE_BYTES + o * A_STRIDE_B + c * 2) = lo;
    } else {
        int t2 = t - 9 * 128 * 128;
        if (t2 < 27 * 9 * 128) {
            int c  = t2 & 127;
            int idx = t2 >> 7;
            int t9 = idx % 9;
            int oc = idx / 9;
            int kh = t9 / 3, kw = t9 - kh * 3;
            float val;
            if (oc < 18) val = w_p[((oc * Cn + c) * 3 + kh) * 3 + kw];
            else         val = w_m[(((oc - 18) * Cn + c) * 3 + kh) * 3 + kw];
            g_wpm[t2] = val;
        }
    }
}

// ---------------------------------------------------------------
// Kernel A: fused offset(18) + mask(9) 3x3 conv, pad 1. FFMA2 inner loop.
__global__ void k_convA(const float* __restrict__ b_p, const float* __restrict__ b_m) {
    extern __shared__ float smem[];
    float* xs = smem;           // 11664 floats
    float* ws = smem + 11664;   // 7776 floats
    u32 xsb = smem_u32(xs);
    u32 wsb = smem_u32(ws);
    int b  = blockIdx.z;
    int h0 = blockIdx.y * 16, w0 = blockIdx.x * 16;
    int tid = threadIdx.x;
    int px = tid & 15, py = tid >> 4;

    u64 acc2[27];
#pragma unroll
    for (int i = 0; i < 27; i++) acc2[i] = 0ull;

    for (int cc = 0; cc < Cn; cc += 32) {
        for (int e = tid; e < 18 * 18 * 32; e += 256) {
            int c   = e & 31;
            int col = (e >> 5) % 18;
            int row = e / (18 * 32);
            int gh = h0 - 1 + row, gw = w0 - 1 + col;
            float val = 0.f;
            if (gh >= 0 && gh < Hh && gw >= 0 && gw < Ww)
                val = g_xt[((b * Hh + gh) * Ww + gw) * Cn + cc + c];
            xs[(row * 18 + col) * 36 + c] = val;
        }
        for (int e = tid; e < 27 * 9 * 32; e += 256)
            ws[e] = g_wpm[(e >> 5) * 128 + cc + (e & 31)];
        __syncthreads();

#pragma unroll 1
        for (int t9 = 0; t9 < 9; t9++) {
            int kh = t9 / 3, kw = t9 - kh * 3;
            u32 xaddr = xsb + (((py + kh) * 18 + (px + kw)) * 36) * 4;
#pragma unroll 1
            for (int c4 = 0; c4 < 8; c4++) {
                u64 x01, x23;
                asm("ld.shared.v2.u64 {%0,%1}, [%2];"
                    : "=l"(x01), "=l"(x23) : "r"(xaddr + c4 * 16));
#pragma unroll
                for (int oc = 0; oc < 27; oc++) {
                    u64 w01, w23;
                    asm("ld.shared.v2.u64 {%0,%1}, [%2];"
                        : "=l"(w01), "=l"(w23)
                        : "r"(wsb + ((oc * 9 + t9) * 32 + c4 * 4) * 4));
                    asm("fma.rn.f32x2 %0, %1, %2, %0;" : "+l"(acc2[oc]) : "l"(x01), "l"(w01));
                    asm("fma.rn.f32x2 %0, %1, %2, %0;" : "+l"(acc2[oc]) : "l"(x23), "l"(w23));
                }
            }
        }
        __syncthreads();
    }

    float acc[27];
#pragma unroll
    for (int i = 0; i < 27; i++) {
        float lo, hi;
        asm("mov.b64 {%0,%1}, %2;" : "=f"(lo), "=f"(hi) : "l"(acc2[i]));
        acc[i] = lo + hi;
    }

    int h = h0 + py, w = w0 + px;
    float* dst = &g_om[((b * Hh + h) * Ww + w) * 27];
#pragma unroll
    for (int ch = 0; ch < 18; ch++) dst[ch] = acc[ch] + b_p[ch];
#pragma unroll
    for (int n = 0; n < 9; n++) {
        float t = acc[18 + n] + b_m[n];
        dst[18 + n] = 1.f / (1.f + expf(-t));
    }
}

// ---------------------------------------------------------------
// Gather one conv-tap k for a 64-pixel (4h x 16w) tile into bf16 hi/lo A tiles.
// 16 warps x 4 px each; lanes cover 128 channels as float4.
__device__ __forceinline__ void gather_tap(int b, int k, int oh0, int ow0,
                                           int lane, int wid,
                                           char* aHi, char* aLo) {
    const float4* xt4 = (const float4*)g_xt;
    int di = k / 3, dj = k - di * 3;
    int dh = (di == 0) ? -1 : 0;
    int iI = (di == 0) ? 2 : (di == 1 ? 0 : 1);
    int dw = (dj == 0) ? -1 : 0;
    int jJ = (dj == 0) ? 2 : (dj == 1 ? 0 : 1);
    int n = iI * 3 + jJ;
#pragma unroll 1
    for (int s = 0; s < 4; s++) {
        int px = wid * 4 + s;
        int ly = px >> 4, lx = px & 15;
        int h = oh0 + ly + dh, w = ow0 + lx + dw;
        float4 sv;
        if (h < 0 || w < 0) {
            sv = make_float4(0.f, 0.f, 0.f, 0.f);
        } else {
            const float* om = &g_om[((b * Hh + h) * Ww + w) * 27];
            float offx = om[n], offy = om[9 + n], mval = om[18 + n];
            float p_x = offx + (float)(iI - 1) + (float)(h + 1);
            float p_y = offy + (float)(jJ - 1) + (float)(w + 1);
            float flx = floorf(p_x), fly = floorf(p_y);
            float ltx = fminf(fmaxf(flx, 0.f), 129.f);
            float lty = fminf(fmaxf(fly, 0.f), 129.f);
            float rbx = fminf(fmaxf(flx + 1.f, 0.f), 129.f);
            float rby = fminf(fmaxf(fly + 1.f, 0.f), 129.f);
            float cpx = fminf(fmaxf(p_x, 0.f), 129.f);
            float cpy = fminf(fmaxf(p_y, 0.f), 129.f);
            float ax  = 1.f + (ltx - cpx);
            float bx_ = 1.f - (rbx - cpx);
            float ay  = 1.f + (lty - cpy);
            float by_ = 1.f - (rby - cpy);
            float wq[4] = { ax * ay * mval, bx_ * by_ * mval, ax * by_ * mval, bx_ * ay * mval };
            float qxf[4] = { ltx, rbx, ltx, rbx };
            float qyf[4] = { lty, rby, rby, lty };
            int base4[4];
#pragma unroll
            for (int j = 0; j < 4; j++) {
                int ix = (int)qxf[j], iy = (int)qyf[j];
                bool valid = (ix >= 1 && ix <= Hh && iy >= 1 && iy <= Ww);
                base4[j] = valid ? (((b * Hh + ix - 1) * Ww + iy - 1) * 32) : 0;
                if (!valid) wq[j] = 0.f;
            }
            float4 a0 = xt4[base4[0] + lane];
            float4 a1 = xt4[base4[1] + lane];
            float4 a2 = xt4[base4[2] + lane];
            float4 a3 = xt4[base4[3] + lane];
            sv.x = wq[0]*a0.x + wq[1]*a1.x + wq[2]*a2.x + wq[3]*a3.x;
            sv.y = wq[0]*a0.y + wq[1]*a1.y + wq[2]*a2.y + wq[3]*a3.y;
            sv.z = wq[0]*a0.z + wq[1]*a1.z + wq[2]*a2.z + wq[3]*a3.z;
            sv.w = wq[0]*a0.w + wq[1]*a1.w + wq[2]*a2.w + wq[3]*a3.w;
        }
        __nv_bfloat162 hA, hB, lA, lB;
        hA.x = __float2bfloat16(sv.x); hA.y = __float2bfloat16(sv.y);
        hB.x = __float2bfloat16(sv.z); hB.y = __float2bfloat16(sv.w);
        lA.x = __float2bfloat16(sv.x - __bfloat162float(hA.x));
        lA.y = __float2bfloat16(sv.y - __bfloat162float(hA.y));
        lB.x = __float2bfloat16(sv.z - __bfloat162float(hB.x));
        lB.y = __float2bfloat16(sv.w - __bfloat162float(hB.y));
        u32 off = (u32)px * A_STRIDE_B + (u32)lane * 8u;  // c = lane*4
        *(uint2*)(aHi + off) = make_uint2(*(u32*)&hA, *(u32*)&hB);
        *(uint2*)(aLo + off) = make_uint2(*(u32*)&lA, *(u32*)&lB);
    }
}

// stage tap-k weights (hi+lo, 69632 B) into smem B buffer via cp.async
__device__ __forceinline__ void cp_b(u32 Bb, int k, int tid) {
    const char* src = (const char*)g_wb2 + k * (2 * B_TILE_BYTES);
#pragma unroll
    for (int i = 0; i < 9; i++) {
        int idx = tid + i * 512;
        if (idx < 4352) {
            asm volatile("cp.async.cg.shared.global [%0], [%1], 16;"
                         :: "r"(Bb + (u32)idx * 16u), "l"(src + idx * 16) : "memory");
        }
    }
    asm volatile("cp.async.commit_group;" ::: "memory");
}

__device__ __forceinline__ void ldm4(u32 addr, u32* r) {
    asm volatile("ldmatrix.sync.aligned.m8n8.x4.shared.b16 {%0,%1,%2,%3}, [%4];"
                 : "=r"(r[0]), "=r"(r[1]), "=r"(r[2]), "=r"(r[3]) : "r"(addr));
}

__device__ __forceinline__ void mma16816(float* c, const u32* a, u32 b0, u32 b1) {
    asm volatile("mma.sync.aligned.m16n8k16.row.col.f32.bf16.bf16.f32 "
                 "{%0,%1,%2,%3}, {%4,%5,%6,%7}, {%8,%9}, {%0,%1,%2,%3};"
                 : "+f"(c[0]), "+f"(c[1]), "+f"(c[2]), "+f"(c[3])
                 : "r"(a[0]), "r"(a[1]), "r"(a[2]), "r"(a[3]), "r"(b0), "r"(b1));
}

// ---------------------------------------------------------------
// Kernel B: deformable gather -> bf16x3 mma.sync GEMM.
// Block 512 thr / 16 warps; tile M=64 px (4h x 16w) x N=128 o; K = 9 taps x 128 c.
// smem: A hi/lo (34816) + B hi/lo (69632) = 104448 B; D epilogue overlays A.
__global__ void __launch_bounds__(512, 2) k_deform(float* __restrict__ out) {
    extern __shared__ char smc[];
    u32 Ab = smem_u32(smc);
    u32 Bb = Ab + SMEM_B_OFF;

    int b   = blockIdx.z;
    int oh0 = blockIdx.y * 4, ow0 = blockIdx.x * 16;
    int tid  = threadIdx.x;
    int lane = tid & 31, wid = tid >> 5;
    int mrow = (wid & 3) * 16;          // pixel-row base of this warp's A tile
    int nb   = (wid >> 2) * 32;         // o base of this warp's B tile

    float acc[16];                      // 4 n8-subtiles x 4
#pragma unroll
    for (int i = 0; i < 16; i++) acc[i] = 0.f;

    // ldmatrix lane addresses
    u32 a_off = (u32)(mrow + (lane & 15)) * A_STRIDE_B + (u32)(lane >> 4) * 16u;
    u32 b_row = (u32)(nb + (lane & 7) + ((lane >> 4) << 3));
    u32 b_off = b_row * A_STRIDE_B + (u32)((lane >> 3) & 1) * 16u;

#pragma unroll 1
    for (int k = 0; k < 9; k++) {
        cp_b(Bb, k, tid);
        gather_tap(b, k, oh0, ow0, lane, wid, smc, smc + A_HI_BYTES);
        asm volatile("cp.async.wait_group 0;" ::: "memory");
        __syncthreads();

#pragma unroll 1
        for (int kk = 0; kk < 8; kk++) {
            u32 koff = (u32)kk * 32u;
            u32 ah[4], al[4];
            ldm4(Ab + a_off + koff, ah);
            ldm4(Ab + (u32)A_HI_BYTES + a_off + koff, al);
#pragma unroll
            for (int ng = 0; ng < 2; ng++) {
                u32 bh[4], bl[4];
                u32 badd = Bb + b_off + (u32)ng * (16u * A_STRIDE_B) + koff;
                ldm4(badd, bh);
                ldm4(badd + (u32)B_TILE_BYTES, bl);
                float* c0 = &acc[(ng * 2 + 0) * 4];
                float* c1 = &acc[(ng * 2 + 1) * 4];
                mma16816(c0, ah, bh[0], bh[1]);
                mma16816(c1, ah, bh[2], bh[3]);
                mma16816(c0, ah, bl[0], bl[1]);
                mma16816(c1, ah, bl[2], bl[3]);
                mma16816(c0, al, bh[0], bh[1]);
                mma16816(c1, al, bh[2], bh[3]);
            }
        }
        __syncthreads();
    }

    // epilogue: frags -> smem d[o][66] -> coalesced global stores
    float* dsm = (float*)smc;
    {
        int g = lane >> 2, t = lane & 3;
#pragma unroll
        for (int si = 0; si < 4; si++) {
            int ob = nb + si * 8;
            dsm[(ob + 2 * t)     * 66 + mrow + g]     = acc[si * 4 + 0];
            dsm[(ob + 2 * t + 1) * 66 + mrow + g]     = acc[si * 4 + 1];
            dsm[(ob + 2 * t)     * 66 + mrow + g + 8] = acc[si * 4 + 2];
            dsm[(ob + 2 * t + 1) * 66 + mrow + g + 8] = acc[si * 4 + 3];
        }
    }
    __syncthreads();
#pragma unroll
    for (int it = 0; it < 16; it++) {
        int idx = tid + it * 512;
        int o = idx >> 6, px = idx & 63;
        out[((b * OC + o) * Hh + oh0 + (px >> 4)) * Ww + ow0 + (px & 15)] = dsm[o * 66 + px];
    }
}

// ---------------------------------------------------------------
extern "C" void kernel_launch(void* const* d_in, const int* in_sizes, int n_in,
                              void* d_out, int out_size) {
    const float* x      = (const float*)d_in[0];
    const float* w_p    = (const float*)d_in[1];
    const float* b_p    = (const float*)d_in[2];
    const float* w_m    = (const float*)d_in[3];
    const float* b_m    = (const float*)d_in[4];
    const float* w_conv = (const float*)d_in[5];
    float* out = (float*)d_out;

    cudaFuncSetAttribute(k_convA,  cudaFuncAttributeMaxDynamicSharedMemorySize, (11664 + 7776) * 4);
    cudaFuncSetAttribute(k_deform, cudaFuncAttributeMaxDynamicSharedMemorySize, SMEM_TOTAL);

    k_transpose_x<<<dim3(4, 4, Bn * Hh), dim3(32, 8)>>>(x);

    int wthreads = 9 * 128 * 128 + 27 * 9 * 128;
    k_transpose_w<<<(wthreads + 255) / 256, 256>>>(w_conv, w_p, w_m);

    k_convA<<<dim3(8, 8, Bn), 256, (11664 + 7776) * 4>>>(b_p, b_m);

    // tile 4(h) x 16(w): grid (W/16, H/4, B)
    k_deform<<<dim3(8, 32, Bn), 512, SMEM_TOTAL>>>(out);
}

// round 7
// speedup vs baseline: 2.8431x; 1.2544x over previous
#include <cuda_runtime.h>
#include <cuda_bf16.h>
#include <math.h>

// Problem constants: B=2, C=128, H=W=128, outc=128, KS=3, N=9, PAD=1
#define Bn 2
#define Cn 128
#define Hh 128
#define Ww 128
#define OC 128

typedef unsigned long long u64;
typedef unsigned int u32;

// -------- scratch (static device globals; no allocation allowed) --------
__device__ float g_xt [Bn*Hh*Ww*Cn];                 // x as [B,H,W,C]
__device__ float g_om [Bn*Hh*Ww*27];                 // 18 offsets + 9 sigmoid(mask)
// w_conv per tap: hi tile (128 o-rows x 136 cols bf16) then lo tile; exact smem image
__device__ __align__(16) unsigned char g_wb2[9*2*34816];
// convA weights per tap: hi tile (32 o-rows x 136 cols bf16) then lo tile (rows 27..31 zero)
__device__ __align__(16) unsigned char g_wcA[9*17408];

#define A_STRIDE_B 272              // 136 bf16 per row
#define A_HI_BYTES 17408            // 64 rows (deform A)
#define B_TILE_BYTES 34816          // 128 rows
#define SMEM_B_OFF 34816            // deform: A hi + A lo
#define SMEM_TOTAL (34816 + 69632)  // deform smem: 104448

#define CA_A_HI 34816               // convA: A hi bytes (128 rows x 272)
#define CA_B_OFF 69632              // convA: B offset (A hi + A lo)
#define CA_B_BYTES 17408            // convA B hi+lo
#define CA_SMEM (69632 + 17408)     // 87040

__device__ __forceinline__ u32 smem_u32(const void* p) {
    u32 a;
    asm("{ .reg .u64 t; cvta.to.shared.u64 t, %1; cvt.u32.u64 %0, t; }" : "=r"(a) : "l"(p));
    return a;
}

__device__ __forceinline__ void ldm4(u32 addr, u32* r) {
    asm volatile("ldmatrix.sync.aligned.m8n8.x4.shared.b16 {%0,%1,%2,%3}, [%4];"
                 : "=r"(r[0]), "=r"(r[1]), "=r"(r[2]), "=r"(r[3]) : "r"(addr));
}

__device__ __forceinline__ void mma16816(float* c, const u32* a, u32 b0, u32 b1) {
    asm volatile("mma.sync.aligned.m16n8k16.row.col.f32.bf16.bf16.f32 "
                 "{%0,%1,%2,%3}, {%4,%5,%6,%7}, {%8,%9}, {%0,%1,%2,%3};"
                 : "+f"(c[0]), "+f"(c[1]), "+f"(c[2]), "+f"(c[3])
                 : "r"(a[0]), "r"(a[1]), "r"(a[2]), "r"(a[3]), "r"(b0), "r"(b1));
}

__device__ __forceinline__ void split_store(float4 sv, char* hiP, char* loP) {
    __nv_bfloat162 hA, hB, lA, lB;
    hA.x = __float2bfloat16(sv.x); hA.y = __float2bfloat16(sv.y);
    hB.x = __float2bfloat16(sv.z); hB.y = __float2bfloat16(sv.w);
    lA.x = __float2bfloat16(sv.x - __bfloat162float(hA.x));
    lA.y = __float2bfloat16(sv.y - __bfloat162float(hA.y));
    lB.x = __float2bfloat16(sv.z - __bfloat162float(hB.x));
    lB.y = __float2bfloat16(sv.w - __bfloat162float(hB.y));
    *(uint2*)hiP = make_uint2(*(u32*)&hA, *(u32*)&hB);
    *(uint2*)loP = make_uint2(*(u32*)&lA, *(u32*)&lB);
}

// ---------------------------------------------------------------
// Kernel 0a: transpose x NCHW -> BHWC
__global__ void k_transpose_x(const float* __restrict__ x) {
    __shared__ float tile[32][33];
    int bxw = blockIdx.x, byc = blockIdx.y, bz = blockIdx.z;
    int b = bz >> 7, h = bz & 127;
    int tx = threadIdx.x, ty = threadIdx.y;
#pragma unroll
    for (int i = 0; i < 4; i++) {
        int c = byc * 32 + ty + i * 8;
        tile[ty + i * 8][tx] = x[((b * Cn + c) * Hh + h) * Ww + bxw * 32 + tx];
    }
    __syncthreads();
#pragma unroll
    for (int i = 0; i < 4; i++) {
        int w = bxw * 32 + ty + i * 8;
        g_xt[((b * Hh + h) * Ww + w) * Cn + byc * 32 + tx] = tile[tx][ty + i * 8];
    }
}

// ---------------------------------------------------------------
// Kernel 0b: weight re-layouts (bf16 hi/lo smem images for both GEMMs)
__global__ void k_transpose_w(const float* __restrict__ w_conv,
                              const float* __restrict__ w_p,
                              const float* __restrict__ w_m) {
    int t = blockIdx.x * blockDim.x + threadIdx.x;
    if (t < 9 * 128 * 128) {
        int c = t & 127;
        int o = (t >> 7) & 127;
        int k = t >> 14;
        int di = k / 3, dj = k - di * 3;
        float val = w_conv[((o * Cn + c) * 3 + di) * 3 + dj];
        __nv_bfloat16 hi = __float2bfloat16(val);
        __nv_bfloat16 lo = __float2bfloat16(val - __bfloat162float(hi));
        unsigned char* base = g_wb2 + k * (2 * B_TILE_BYTES);
        *(__nv_bfloat16*)(base + o * A_STRIDE_B + c * 2) = hi;
        *(__nv_bfloat16*)(base + B_TILE_BYTES + o * A_STRIDE_B + c * 2) = lo;
    } else {
        int t2 = t - 9 * 128 * 128;
        if (t2 < 9 * 27 * 128) {
            int c = t2 & 127;
            int rest = t2 >> 7;
            int o = rest % 27;
            int k = rest / 27;
            int kh = k / 3, kw = k - kh * 3;
            float val;
            if (o < 18) val = w_p[((o * Cn + c) * 3 + kh) * 3 + kw];
            else        val = w_m[(((o - 18) * Cn + c) * 3 + kh) * 3 + kw];
            __nv_bfloat16 hi = __float2bfloat16(val);
            __nv_bfloat16 lo = __float2bfloat16(val - __bfloat162float(hi));
            unsigned char* base = g_wcA + k * CA_B_BYTES;
            *(__nv_bfloat16*)(base + o * A_STRIDE_B + c * 2) = hi;
            *(__nv_bfloat16*)(base + 8704 + o * A_STRIDE_B + c * 2) = lo;
        }
    }
}

// ---------------------------------------------------------------
// Kernel A: fused offset(18) + mask(9) 3x3 conv via bf16x3 mma.sync.
// Block 256 thr / 8 warps; tile M=128 px (8h x 16w) x N=32 (27 used); K = 9 taps x 128 c.
// smem: A hi/lo (69632) + B hi/lo (17408) = 87040; epilogue dsm overlays A.
__global__ void __launch_bounds__(256, 2) k_convA(const float* __restrict__ b_p,
                                                  const float* __restrict__ b_m) {
    extern __shared__ char smc[];
    u32 Ab = smem_u32(smc);
    u32 Bb = Ab + CA_B_OFF;

    int b  = blockIdx.z;
    int h0 = blockIdx.y * 8, w0 = blockIdx.x * 16;
    int tid = threadIdx.x;
    int lane = tid & 31, wid = tid >> 5;
    int mrow = wid * 16;

    const float4* xt4 = (const float4*)g_xt;

    float acc[16];
#pragma unroll
    for (int i = 0; i < 16; i++) acc[i] = 0.f;

    u32 a_off = (u32)(mrow + (lane & 15)) * A_STRIDE_B + (u32)(lane >> 4) * 16u;
    u32 b_off = (u32)((lane & 7) + ((lane >> 4) << 3)) * A_STRIDE_B
              + (u32)((lane >> 3) & 1) * 16u;

#pragma unroll 1
    for (int t9 = 0; t9 < 9; t9++) {
        int kh = t9 / 3, kw = t9 - kh * 3;
        // stage B (hi+lo, 17408 B = 1088 x 16B)
        {
            const char* src = (const char*)g_wcA + t9 * CA_B_BYTES;
#pragma unroll
            for (int i = 0; i < 5; i++) {
                int idx = tid + i * 256;
                if (idx < 1088) {
                    asm volatile("cp.async.cg.shared.global [%0], [%1], 16;"
                                 :: "r"(Bb + (u32)idx * 16u), "l"(src + idx * 16) : "memory");
                }
            }
            asm volatile("cp.async.commit_group;" ::: "memory");
        }
        // load A: shifted x reads, each warp 16 px
#pragma unroll 1
        for (int s = 0; s < 16; s++) {
            int px = wid * 16 + s;
            int h = h0 + (px >> 4) + kh - 1;
            int w = w0 + (px & 15) + kw - 1;
            float4 sv = make_float4(0.f, 0.f, 0.f, 0.f);
            if (h >= 0 && h < Hh && w >= 0 && w < Ww)
                sv = xt4[((b * Hh + h) * Ww + w) * 32 + lane];
            u32 off = (u32)px * A_STRIDE_B + (u32)lane * 8u;
            split_store(sv, smc + off, smc + CA_A_HI + off);
        }
        asm volatile("cp.async.wait_group 0;" ::: "memory");
        __syncthreads();

#pragma unroll 1
        for (int kk = 0; kk < 8; kk++) {
            u32 koff = (u32)kk * 32u;
            u32 ah[4], al[4];
            ldm4(Ab + a_off + koff, ah);
            ldm4(Ab + (u32)CA_A_HI + a_off + koff, al);
#pragma unroll
            for (int ng = 0; ng < 2; ng++) {
                u32 bh[4], bl[4];
                u32 badd = Bb + b_off + (u32)ng * (16u * A_STRIDE_B) + koff;
                ldm4(badd, bh);
                ldm4(badd + 8704u, bl);
                float* c0 = &acc[(ng * 2 + 0) * 4];
                float* c1 = &acc[(ng * 2 + 1) * 4];
                mma16816(c0, ah, bh[0], bh[1]);
                mma16816(c1, ah, bh[2], bh[3]);
                mma16816(c0, ah, bl[0], bl[1]);
                mma16816(c1, ah, bl[2], bl[3]);
                mma16816(c0, al, bh[0], bh[1]);
                mma16816(c1, al, bh[2], bh[3]);
            }
        }
        __syncthreads();
    }

    // epilogue: frags -> dsm[px][33] -> bias/sigmoid -> g_om
    float* dsm = (float*)smc;
    {
        int g = lane >> 2, t = lane & 3;
#pragma unroll
        for (int si = 0; si < 4; si++) {
            int ob = si * 8;
            dsm[(mrow + g)     * 33 + ob + 2 * t]     = acc[si * 4 + 0];
            dsm[(mrow + g)     * 33 + ob + 2 * t + 1] = acc[si * 4 + 1];
            dsm[(mrow + g + 8) * 33 + ob + 2 * t]     = acc[si * 4 + 2];
            dsm[(mrow + g + 8) * 33 + ob + 2 * t + 1] = acc[si * 4 + 3];
        }
    }
    __syncthreads();
    for (int idx = tid; idx < 128 * 27; idx += 256) {
        int px = idx / 27, o = idx - px * 27;
        float val = dsm[px * 33 + o];
        int h = h0 + (px >> 4), w = w0 + (px & 15);
        float r;
        if (o < 18) r = val + b_p[o];
        else        r = 1.f / (1.f + expf(-(val + b_m[o - 18])));
        g_om[((b * Hh + h) * Ww + w) * 27 + o] = r;
    }
}

// ---------------------------------------------------------------
// Gather one conv-tap k for a 64-pixel (4h x 16w) tile into bf16 hi/lo A tiles.
// 16 warps x 4 px each; lanes cover 128 channels as float4.
__device__ __forceinline__ void gather_tap(int b, int k, int oh0, int ow0,
                                           int lane, int wid,
                                           char* aHi, char* aLo) {
    const float4* xt4 = (const float4*)g_xt;
    int di = k / 3, dj = k - di * 3;
    int dh = (di == 0) ? -1 : 0;
    int iI = (di == 0) ? 2 : (di == 1 ? 0 : 1);
    int dw = (dj == 0) ? -1 : 0;
    int jJ = (dj == 0) ? 2 : (dj == 1 ? 0 : 1);
    int n = iI * 3 + jJ;
#pragma unroll 1
    for (int s = 0; s < 4; s++) {
        int px = wid * 4 + s;
        int ly = px >> 4, lx = px & 15;
        int h = oh0 + ly + dh, w = ow0 + lx + dw;
        float4 sv;
        if (h < 0 || w < 0) {
            sv = make_float4(0.f, 0.f, 0.f, 0.f);
        } else {
            const float* om = &g_om[((b * Hh + h) * Ww + w) * 27];
            float offx = om[n], offy = om[9 + n], mval = om[18 + n];
            float p_x = offx + (float)(iI - 1) + (float)(h + 1);
            float p_y = offy + (float)(jJ - 1) + (float)(w + 1);
            float flx = floorf(p_x), fly = floorf(p_y);
            float ltx = fminf(fmaxf(flx, 0.f), 129.f);
            float lty = fminf(fmaxf(fly, 0.f), 129.f);
            float rbx = fminf(fmaxf(flx + 1.f, 0.f), 129.f);
            float rby = fminf(fmaxf(fly + 1.f, 0.f), 129.f);
            float cpx = fminf(fmaxf(p_x, 0.f), 129.f);
            float cpy = fminf(fmaxf(p_y, 0.f), 129.f);
            float ax  = 1.f + (ltx - cpx);
            float bx_ = 1.f - (rbx - cpx);
            float ay  = 1.f + (lty - cpy);
            float by_ = 1.f - (rby - cpy);
            float wq[4] = { ax * ay * mval, bx_ * by_ * mval, ax * by_ * mval, bx_ * ay * mval };
            float qxf[4] = { ltx, rbx, ltx, rbx };
            float qyf[4] = { lty, rby, rby, lty };
            int base4[4];
#pragma unroll
            for (int j = 0; j < 4; j++) {
                int ix = (int)qxf[j], iy = (int)qyf[j];
                bool valid = (ix >= 1 && ix <= Hh && iy >= 1 && iy <= Ww);
                base4[j] = valid ? (((b * Hh + ix - 1) * Ww + iy - 1) * 32) : 0;
                if (!valid) wq[j] = 0.f;
            }
            float4 a0 = xt4[base4[0] + lane];
            float4 a1 = xt4[base4[1] + lane];
            float4 a2 = xt4[base4[2] + lane];
            float4 a3 = xt4[base4[3] + lane];
            sv.x = wq[0]*a0.x + wq[1]*a1.x + wq[2]*a2.x + wq[3]*a3.x;
            sv.y = wq[0]*a0.y + wq[1]*a1.y + wq[2]*a2.y + wq[3]*a3.y;
            sv.z = wq[0]*a0.z + wq[1]*a1.z + wq[2]*a2.z + wq[3]*a3.z;
            sv.w = wq[0]*a0.w + wq[1]*a1.w + wq[2]*a2.w + wq[3]*a3.w;
        }
        u32 off = (u32)px * A_STRIDE_B + (u32)lane * 8u;
        split_store(sv, aHi + off, aLo + off);
    }
}

// stage tap-k deform weights (hi+lo, 69632 B) into smem B buffer via cp.async
__device__ __forceinline__ void cp_b(u32 Bb, int k, int tid) {
    const char* src = (const char*)g_wb2 + k * (2 * B_TILE_BYTES);
#pragma unroll
    for (int i = 0; i < 9; i++) {
        int idx = tid + i * 512;
        if (idx < 4352) {
            asm volatile("cp.async.cg.shared.global [%0], [%1], 16;"
                         :: "r"(Bb + (u32)idx * 16u), "l"(src + idx * 16) : "memory");
        }
    }
    asm volatile("cp.async.commit_group;" ::: "memory");
}

// ---------------------------------------------------------------
// Kernel B: deformable gather -> bf16x3 mma.sync GEMM.
// Block 512 thr / 16 warps; tile M=64 px (4h x 16w) x N=128 o; K = 9 taps x 128 c.
__global__ void __launch_bounds__(512, 2) k_deform(float* __restrict__ out) {
    extern __shared__ char smc[];
    u32 Ab = smem_u32(smc);
    u32 Bb = Ab + SMEM_B_OFF;

    int b   = blockIdx.z;
    int oh0 = blockIdx.y * 4, ow0 = blockIdx.x * 16;
    int tid  = threadIdx.x;
    int lane = tid & 31, wid = tid >> 5;
    int mrow = (wid & 3) * 16;
    int nb   = (wid >> 2) * 32;

    float acc[16];
#pragma unroll
    for (int i = 0; i < 16; i++) acc[i] = 0.f;

    u32 a_off = (u32)(mrow + (lane & 15)) * A_STRIDE_B + (u32)(lane >> 4) * 16u;
    u32 b_row = (u32)(nb + (lane & 7) + ((lane >> 4) << 3));
    u32 b_off = b_row * A_STRIDE_B + (u32)((lane >> 3) & 1) * 16u;

#pragma unroll 1
    for (int k = 0; k < 9; k++) {
        cp_b(Bb, k, tid);
        gather_tap(b, k, oh0, ow0, lane, wid, smc, smc + A_HI_BYTES);
        asm volatile("cp.async.wait_group 0;" ::: "memory");
        __syncthreads();

#pragma unroll 1
        for (int kk = 0; kk < 8; kk++) {
            u32 koff = (u32)kk * 32u;
            u32 ah[4], al[4];
            ldm4(Ab + a_off + koff, ah);
            ldm4(Ab + (u32)A_HI_BYTES + a_off + koff, al);
#pragma unroll
            for (int ng = 0; ng < 2; ng++) {
                u32 bh[4], bl[4];
                u32 badd = Bb + b_off + (u32)ng * (16u * A_STRIDE_B) + koff;
                ldm4(badd, bh);
                ldm4(badd + (u32)B_TILE_BYTES, bl);
                float* c0 = &acc[(ng * 2 + 0) * 4];
                float* c1 = &acc[(ng * 2 + 1) * 4];
                mma16816(c0, ah, bh[0], bh[1]);
                mma16816(c1, ah, bh[2], bh[3]);
                mma16816(c0, ah, bl[0], bl[1]);
                mma16816(c1, ah, bl[2], bl[3]);
                mma16816(c0, al, bh[0], bh[1]);
                mma16816(c1, al, bh[2], bh[3]);
            }
        }
        __syncthreads();
    }

    // epilogue: frags -> smem d[o][66] -> coalesced global stores
    float* dsm = (float*)smc;
    {
        int g = lane >> 2, t = lane & 3;
#pragma unroll
        for (int si = 0; si < 4; si++) {
            int ob = nb + si * 8;
            dsm[(ob + 2 * t)     * 66 + mrow + g]     = acc[si * 4 + 0];
            dsm[(ob + 2 * t + 1) * 66 + mrow + g]     = acc[si * 4 + 1];
            dsm[(ob + 2 * t)     * 66 + mrow + g + 8] = acc[si * 4 + 2];
            dsm[(ob + 2 * t + 1) * 66 + mrow + g + 8] = acc[si * 4 + 3];
        }
    }
    __syncthreads();
#pragma unroll
    for (int it = 0; it < 16; it++) {
        int idx = tid + it * 512;
        int o = idx >> 6, px = idx & 63;
        out[((b * OC + o) * Hh + oh0 + (px >> 4)) * Ww + ow0 + (px & 15)] = dsm[o * 66 + px];
    }
}

// ---------------------------------------------------------------
extern "C" void kernel_launch(void* const* d_in, const int* in_sizes, int n_in,
                              void* d_out, int out_size) {
    const float* x      = (const float*)d_in[0];
    const float* w_p    = (const float*)d_in[1];
    const float* b_p    = (const float*)d_in[2];
    const float* w_m    = (const float*)d_in[3];
    const float* b_m    = (const float*)d_in[4];
    const float* w_conv = (const float*)d_in[5];
    float* out = (float*)d_out;

    cudaFuncSetAttribute(k_convA,  cudaFuncAttributeMaxDynamicSharedMemorySize, CA_SMEM);
    cudaFuncSetAttribute(k_deform, cudaFuncAttributeMaxDynamicSharedMemorySize, SMEM_TOTAL);

    k_transpose_x<<<dim3(4, 4, Bn * Hh), dim3(32, 8)>>>(x);

    int wthreads = 9 * 128 * 128 + 9 * 27 * 128;
    k_transpose_w<<<(wthreads + 255) / 256, 256>>>(w_conv, w_p, w_m);

    // convA: tile 8(h) x 16(w): grid (W/16, H/8, B)
    k_convA<<<dim3(8, 16, Bn), 256, CA_SMEM>>>(b_p, b_m);

    // deform: tile 4(h) x 16(w): grid (W/16, H/4, B)
    k_deform<<<dim3(8, 32, Bn), 512, SMEM_TOTAL>>>(out);
}

// round 8
// speedup vs baseline: 3.3721x; 1.1860x over previous
#include <cuda_runtime.h>
#include <cuda_bf16.h>
#include <math.h>

// Problem constants: B=2, C=128, H=W=128, outc=128, KS=3, N=9, PAD=1
#define Bn 2
#define Cn 128
#define Hh 128
#define Ww 128
#define OC 128

typedef unsigned long long u64;
typedef unsigned int u32;

// -------- scratch (static device globals; no allocation allowed) --------
__device__ float g_xt [Bn*Hh*Ww*Cn];                 // x as [B,H,W,C]
__device__ float g_om [Bn*Hh*Ww*27];                 // 18 offsets + 9 sigmoid(mask)
// w_conv per tap: hi tile (128 o-rows x 136 cols bf16) then lo tile; exact smem image
__device__ __align__(16) unsigned char g_wb2[9*2*34816];
// convA weights per tap: hi tile (32 o-rows x 136 cols bf16) then lo tile (rows 27..31 zero)
__device__ __align__(16) unsigned char g_wcA[9*17408];

#define A_STRIDE_B 272              // 136 bf16 per row
#define A_HI_BYTES 17408            // 64 rows (deform A)
#define B_TILE_BYTES 34816          // 128 rows
#define SMEM_B_OFF 34816            // deform: A hi + A lo
#define SMEM_TOTAL (34816 + 69632)  // deform smem: 104448

// convA (halo version): 18x18 = 324 halo rows
#define CA_HALO_ROWS 324
#define CA_HALO_BYTES (324 * 272)   // 88128
#define CA_B_OFF (2 * 88128)        // 176256
#define CA_B_BYTES 17408            // one tap's B (hi 8704 + lo 8704)
#define CA_SMEM (176256 + 2 * 17408) // 211072

__device__ __forceinline__ u32 smem_u32(const void* p) {
    u32 a;
    asm("{ .reg .u64 t; cvta.to.shared.u64 t, %1; cvt.u32.u64 %0, t; }" : "=r"(a) : "l"(p));
    return a;
}

__device__ __forceinline__ void ldm4(u32 addr, u32* r) {
    asm volatile("ldmatrix.sync.aligned.m8n8.x4.shared.b16 {%0,%1,%2,%3}, [%4];"
                 : "=r"(r[0]), "=r"(r[1]), "=r"(r[2]), "=r"(r[3]) : "r"(addr));
}

__device__ __forceinline__ void mma16816(float* c, const u32* a, u32 b0, u32 b1) {
    asm volatile("mma.sync.aligned.m16n8k16.row.col.f32.bf16.bf16.f32 "
                 "{%0,%1,%2,%3}, {%4,%5,%6,%7}, {%8,%9}, {%0,%1,%2,%3};"
                 : "+f"(c[0]), "+f"(c[1]), "+f"(c[2]), "+f"(c[3])
                 : "r"(a[0]), "r"(a[1]), "r"(a[2]), "r"(a[3]), "r"(b0), "r"(b1));
}

__device__ __forceinline__ void split_store(float4 sv, char* hiP, char* loP) {
    __nv_bfloat162 hA, hB, lA, lB;
    hA.x = __float2bfloat16(sv.x); hA.y = __float2bfloat16(sv.y);
    hB.x = __float2bfloat16(sv.z); hB.y = __float2bfloat16(sv.w);
    lA.x = __float2bfloat16(sv.x - __bfloat162float(hA.x));
    lA.y = __float2bfloat16(sv.y - __bfloat162float(hA.y));
    lB.x = __float2bfloat16(sv.z - __bfloat162float(hB.x));
    lB.y = __float2bfloat16(sv.w - __bfloat162float(hB.y));
    *(uint2*)hiP = make_uint2(*(u32*)&hA, *(u32*)&hB);
    *(uint2*)loP = make_uint2(*(u32*)&lA, *(u32*)&lB);
}

// ---------------------------------------------------------------
// Kernel 0a: transpose x NCHW -> BHWC
__global__ void k_transpose_x(const float* __restrict__ x) {
    __shared__ float tile[32][33];
    int bxw = blockIdx.x, byc = blockIdx.y, bz = blockIdx.z;
    int b = bz >> 7, h = bz & 127;
    int tx = threadIdx.x, ty = threadIdx.y;
#pragma unroll
    for (int i = 0; i < 4; i++) {
        int c = byc * 32 + ty + i * 8;
        tile[ty + i * 8][tx] = x[((b * Cn + c) * Hh + h) * Ww + bxw * 32 + tx];
    }
    __syncthreads();
#pragma unroll
    for (int i = 0; i < 4; i++) {
        int w = bxw * 32 + ty + i * 8;
        g_xt[((b * Hh + h) * Ww + w) * Cn + byc * 32 + tx] = tile[tx][ty + i * 8];
    }
}

// ---------------------------------------------------------------
// Kernel 0b: weight re-layouts (bf16 hi/lo smem images for both GEMMs)
__global__ void k_transpose_w(const float* __restrict__ w_conv,
                              const float* __restrict__ w_p,
                              const float* __restrict__ w_m) {
    int t = blockIdx.x * blockDim.x + threadIdx.x;
    if (t < 9 * 128 * 128) {
        int c = t & 127;
        int o = (t >> 7) & 127;
        int k = t >> 14;
        int di = k / 3, dj = k - di * 3;
        float val = w_conv[((o * Cn + c) * 3 + di) * 3 + dj];
        __nv_bfloat16 hi = __float2bfloat16(val);
        __nv_bfloat16 lo = __float2bfloat16(val - __bfloat162float(hi));
        unsigned char* base = g_wb2 + k * (2 * B_TILE_BYTES);
        *(__nv_bfloat16*)(base + o * A_STRIDE_B + c * 2) = hi;
        *(__nv_bfloat16*)(base + B_TILE_BYTES + o * A_STRIDE_B + c * 2) = lo;
    } else {
        int t2 = t - 9 * 128 * 128;
        if (t2 < 9 * 27 * 128) {
            int c = t2 & 127;
            int rest = t2 >> 7;
            int o = rest % 27;
            int k = rest / 27;
            int kh = k / 3, kw = k - kh * 3;
            float val;
            if (o < 18) val = w_p[((o * Cn + c) * 3 + kh) * 3 + kw];
            else        val = w_m[(((o - 18) * Cn + c) * 3 + kh) * 3 + kw];
            __nv_bfloat16 hi = __float2bfloat16(val);
            __nv_bfloat16 lo = __float2bfloat16(val - __bfloat162float(hi));
            unsigned char* base = g_wcA + k * CA_B_BYTES;
            *(__nv_bfloat16*)(base + o * A_STRIDE_B + c * 2) = hi;
            *(__nv_bfloat16*)(base + 8704 + o * A_STRIDE_B + c * 2) = lo;
        }
    }
}

// stage tap-k convA weights (hi+lo, 17408 B = 1088 x 16B) via cp.async
__device__ __forceinline__ void cp_bA(u32 Bb, int k, int tid) {
    const char* src = (const char*)g_wcA + k * CA_B_BYTES;
#pragma unroll
    for (int i = 0; i < 3; i++) {
        int idx = tid + i * 512;
        if (idx < 1088) {
            asm volatile("cp.async.cg.shared.global [%0], [%1], 16;"
                         :: "r"(Bb + (u32)idx * 16u), "l"(src + idx * 16) : "memory");
        }
    }
    asm volatile("cp.async.commit_group;" ::: "memory");
}

// ---------------------------------------------------------------
// Kernel A: fused offset(18) + mask(9) 3x3 conv via bf16x3 mma.sync + smem halo.
// Block 512 thr / 16 warps; tile M=256 px (16h x 16w) x N=32 (27 used).
// The 18x18-pixel halo is loaded/split ONCE; each tap's A is just shifted
// ldmatrix row addressing into the halo. B double-buffered via cp.async.
// smem: halo hi/lo (176256) + B[2] (34816) = 211072. Grid = 128 CTAs (1 wave).
__global__ void __launch_bounds__(512, 1) k_convA(const float* __restrict__ b_p,
                                                  const float* __restrict__ b_m) {
    extern __shared__ char smc[];
    u32 Ab = smem_u32(smc);
    u32 Bb = Ab + CA_B_OFF;

    int b  = blockIdx.z;
    int h0 = blockIdx.y * 16, w0 = blockIdx.x * 16;
    int tid = threadIdx.x;
    int lane = tid & 31, wid = tid >> 5;
    int mrow = wid * 16;

    const float4* xt4 = (const float4*)g_xt;

    // stage B(0) first so it overlaps the halo build
    cp_bA(Bb, 0, tid);

    // build halo: 324 rows, one warp-row at a time (lane = 4-channel group)
    for (int r = wid; r < CA_HALO_ROWS; r += 16) {
        int hy = r / 18, hx = r - hy * 18;
        int h = h0 - 1 + hy, w = w0 - 1 + hx;
        float4 sv = make_float4(0.f, 0.f, 0.f, 0.f);
        if (h >= 0 && h < Hh && w >= 0 && w < Ww)
            sv = xt4[((b * Hh + h) * Ww + w) * 32 + lane];
        u32 off = (u32)r * A_STRIDE_B + (u32)lane * 8u;
        split_store(sv, smc + off, smc + CA_HALO_BYTES + off);
    }
    asm volatile("cp.async.wait_group 0;" ::: "memory");
    __syncthreads();

    float acc[16];
#pragma unroll
    for (int i = 0; i < 16; i++) acc[i] = 0.f;

    // per-lane A base pieces: pixel row this lane fetches
    int px_l = mrow + (lane & 15);
    int ly_l = px_l >> 4, lx_l = px_l & 15;
    u32 a_chunk = (u32)(lane >> 4) * 16u;
    u32 b_off = (u32)((lane & 7) + ((lane >> 4) << 3)) * A_STRIDE_B
              + (u32)((lane >> 3) & 1) * 16u;

#pragma unroll 1
    for (int t9 = 0; t9 < 9; t9++) {
        int kh = t9 / 3, kw = t9 - kh * 3;
        if (t9 < 8) cp_bA(Bb + (u32)(((t9 + 1) & 1) * CA_B_BYTES), t9 + 1, tid);
        u32 Bcur = Bb + (u32)((t9 & 1) * CA_B_BYTES);

        // shifted halo row for this lane & tap
        u32 hrow = (u32)((ly_l + kh) * 18 + lx_l + kw);
        u32 a_base = hrow * A_STRIDE_B + a_chunk;

#pragma unroll 1
        for (int kk = 0; kk < 8; kk++) {
            u32 koff = (u32)kk * 32u;
            u32 ah[4], al[4];
            ldm4(Ab + a_base + koff, ah);
            ldm4(Ab + (u32)CA_HALO_BYTES + a_base + koff, al);
#pragma unroll
            for (int ng = 0; ng < 2; ng++) {
                u32 bh[4], bl[4];
                u32 badd = Bcur + b_off + (u32)ng * (16u * A_STRIDE_B) + koff;
                ldm4(badd, bh);
                ldm4(badd + 8704u, bl);
                float* c0 = &acc[(ng * 2 + 0) * 4];
                float* c1 = &acc[(ng * 2 + 1) * 4];
                mma16816(c0, ah, bh[0], bh[1]);
                mma16816(c1, ah, bh[2], bh[3]);
                mma16816(c0, ah, bl[0], bl[1]);
                mma16816(c1, ah, bl[2], bl[3]);
                mma16816(c0, al, bh[0], bh[1]);
                mma16816(c1, al, bh[2], bh[3]);
            }
        }
        if (t9 < 8) {
            asm volatile("cp.async.wait_group 0;" ::: "memory");
            __syncthreads();
        }
    }
    __syncthreads();

    // epilogue: frags -> dsm[px][33] -> bias/sigmoid -> g_om  (dsm overlays halo)
    float* dsm = (float*)smc;
    {
        int g = lane >> 2, t = lane & 3;
#pragma unroll
        for (int si = 0; si < 4; si++) {
            int ob = si * 8;
            dsm[(mrow + g)     * 33 + ob + 2 * t]     = acc[si * 4 + 0];
            dsm[(mrow + g)     * 33 + ob + 2 * t + 1] = acc[si * 4 + 1];
            dsm[(mrow + g + 8) * 33 + ob + 2 * t]     = acc[si * 4 + 2];
            dsm[(mrow + g + 8) * 33 + ob + 2 * t + 1] = acc[si * 4 + 3];
        }
    }
    __syncthreads();
    for (int idx = tid; idx < 256 * 27; idx += 512) {
        int px = idx / 27, o = idx - px * 27;
        float val = dsm[px * 33 + o];
        int h = h0 + (px >> 4), w = w0 + (px & 15);
        float r;
        if (o < 18) r = val + b_p[o];
        else        r = 1.f / (1.f + expf(-(val + b_m[o - 18])));
        g_om[((b * Hh + h) * Ww + w) * 27 + o] = r;
    }
}

// ---------------------------------------------------------------
// Gather one conv-tap k for a 64-pixel (4h x 16w) tile into bf16 hi/lo A tiles.
// 16 warps x 4 px each; lanes cover 128 channels as float4.
__device__ __forceinline__ void gather_tap(int b, int k, int oh0, int ow0,
                                           int lane, int wid,
                                           char* aHi, char* aLo) {
    const float4* xt4 = (const float4*)g_xt;
    int di = k / 3, dj = k - di * 3;
    int dh = (di == 0) ? -1 : 0;
    int iI = (di == 0) ? 2 : (di == 1 ? 0 : 1);
    int dw = (dj == 0) ? -1 : 0;
    int jJ = (dj == 0) ? 2 : (dj == 1 ? 0 : 1);
    int n = iI * 3 + jJ;
#pragma unroll 1
    for (int s = 0; s < 4; s++) {
        int px = wid * 4 + s;
        int ly = px >> 4, lx = px & 15;
        int h = oh0 + ly + dh, w = ow0 + lx + dw;
        float4 sv;
        if (h < 0 || w < 0) {
            sv = make_float4(0.f, 0.f, 0.f, 0.f);
        } else {
            const float* om = &g_om[((b * Hh + h) * Ww + w) * 27];
            float offx = om[n], offy = om[9 + n], mval = om[18 + n];
            float p_x = offx + (float)(iI - 1) + (float)(h + 1);
            float p_y = offy + (float)(jJ - 1) + (float)(w + 1);
            float flx = floorf(p_x), fly = floorf(p_y);
            float ltx = fminf(fmaxf(flx, 0.f), 129.f);
            float lty = fminf(fmaxf(fly, 0.f), 129.f);
            float rbx = fminf(fmaxf(flx + 1.f, 0.f), 129.f);
            float rby = fminf(fmaxf(fly + 1.f, 0.f), 129.f);
            float cpx = fminf(fmaxf(p_x, 0.f), 129.f);
            float cpy = fminf(fmaxf(p_y, 0.f), 129.f);
            float ax  = 1.f + (ltx - cpx);
            float bx_ = 1.f - (rbx - cpx);
            float ay  = 1.f + (lty - cpy);
            float by_ = 1.f - (rby - cpy);
            float wq[4] = { ax * ay * mval, bx_ * by_ * mval, ax * by_ * mval, bx_ * ay * mval };
            float qxf[4] = { ltx, rbx, ltx, rbx };
            float qyf[4] = { lty, rby, rby, lty };
            int base4[4];
#pragma unroll
            for (int j = 0; j < 4; j++) {
                int ix = (int)qxf[j], iy = (int)qyf[j];
                bool valid = (ix >= 1 && ix <= Hh && iy >= 1 && iy <= Ww);
                base4[j] = valid ? (((b * Hh + ix - 1) * Ww + iy - 1) * 32) : 0;
                if (!valid) wq[j] = 0.f;
            }
            float4 a0 = xt4[base4[0] + lane];
            float4 a1 = xt4[base4[1] + lane];
            float4 a2 = xt4[base4[2] + lane];
            float4 a3 = xt4[base4[3] + lane];
            sv.x = wq[0]*a0.x + wq[1]*a1.x + wq[2]*a2.x + wq[3]*a3.x;
            sv.y = wq[0]*a0.y + wq[1]*a1.y + wq[2]*a2.y + wq[3]*a3.y;
            sv.z = wq[0]*a0.z + wq[1]*a1.z + wq[2]*a2.z + wq[3]*a3.z;
            sv.w = wq[0]*a0.w + wq[1]*a1.w + wq[2]*a2.w + wq[3]*a3.w;
        }
        u32 off = (u32)px * A_STRIDE_B + (u32)lane * 8u;
        split_store(sv, aHi + off, aLo + off);
    }
}

// stage tap-k deform weights (hi+lo, 69632 B) into smem B buffer via cp.async
__device__ __forceinline__ void cp_b(u32 Bb, int k, int tid) {
    const char* src = (const char*)g_wb2 + k * (2 * B_TILE_BYTES);
#pragma unroll
    for (int i = 0; i < 9; i++) {
        int idx = tid + i * 512;
        if (idx < 4352) {
            asm volatile("cp.async.cg.shared.global [%0], [%1], 16;"
                         :: "r"(Bb + (u32)idx * 16u), "l"(src + idx * 16) : "memory");
        }
    }
    asm volatile("cp.async.commit_group;" ::: "memory");
}

// ---------------------------------------------------------------
// Kernel B: deformable gather -> bf16x3 mma.sync GEMM.
// Block 512 thr / 16 warps; tile M=64 px (4h x 16w) x N=128 o; K = 9 taps x 128 c.
__global__ void __launch_bounds__(512, 2) k_deform(float* __restrict__ out) {
    extern __shared__ char smc[];
    u32 Ab = smem_u32(smc);
    u32 Bb = Ab + SMEM_B_OFF;

    int b   = blockIdx.z;
    int oh0 = blockIdx.y * 4, ow0 = blockIdx.x * 16;
    int tid  = threadIdx.x;
    int lane = tid & 31, wid = tid >> 5;
    int mrow = (wid & 3) * 16;
    int nb   = (wid >> 2) * 32;

    float acc[16];
#pragma unroll
    for (int i = 0; i < 16; i++) acc[i] = 0.f;

    u32 a_off = (u32)(mrow + (lane & 15)) * A_STRIDE_B + (u32)(lane >> 4) * 16u;
    u32 b_row = (u32)(nb + (lane & 7) + ((lane >> 4) << 3));
    u32 b_off = b_row * A_STRIDE_B + (u32)((lane >> 3) & 1) * 16u;

#pragma unroll 1
    for (int k = 0; k < 9; k++) {
        cp_b(Bb, k, tid);
        gather_tap(b, k, oh0, ow0, lane, wid, smc, smc + A_HI_BYTES);
        asm volatile("cp.async.wait_group 0;" ::: "memory");
        __syncthreads();

#pragma unroll 1
        for (int kk = 0; kk < 8; kk++) {
            u32 koff = (u32)kk * 32u;
            u32 ah[4], al[4];
            ldm4(Ab + a_off + koff, ah);
            ldm4(Ab + (u32)A_HI_BYTES + a_off + koff, al);
#pragma unroll
            for (int ng = 0; ng < 2; ng++) {
                u32 bh[4], bl[4];
                u32 badd = Bb + b_off + (u32)ng * (16u * A_STRIDE_B) + koff;
                ldm4(badd, bh);
                ldm4(badd + (u32)B_TILE_BYTES, bl);
                float* c0 = &acc[(ng * 2 + 0) * 4];
                float* c1 = &acc[(ng * 2 + 1) * 4];
                mma16816(c0, ah, bh[0], bh[1]);
                mma16816(c1, ah, bh[2], bh[3]);
                mma16816(c0, ah, bl[0], bl[1]);
                mma16816(c1, ah, bl[2], bl[3]);
                mma16816(c0, al, bh[0], bh[1]);
                mma16816(c1, al, bh[2], bh[3]);
            }
        }
        __syncthreads();
    }

    // epilogue: frags -> smem d[o][66] -> coalesced global stores
    float* dsm = (float*)smc;
    {
        int g = lane >> 2, t = lane & 3;
#pragma unroll
        for (int si = 0; si < 4; si++) {
            int ob = nb + si * 8;
            dsm[(ob + 2 * t)     * 66 + mrow + g]     = acc[si * 4 + 0];
            dsm[(ob + 2 * t + 1) * 66 + mrow + g]     = acc[si * 4 + 1];
            dsm[(ob + 2 * t)     * 66 + mrow + g + 8] = acc[si * 4 + 2];
            dsm[(ob + 2 * t + 1) * 66 + mrow + g + 8] = acc[si * 4 + 3];
        }
    }
    __syncthreads();
#pragma unroll
    for (int it = 0; it < 16; it++) {
        int idx = tid + it * 512;
        int o = idx >> 6, px = idx & 63;
        out[((b * OC + o) * Hh + oh0 + (px >> 4)) * Ww + ow0 + (px & 15)] = dsm[o * 66 + px];
    }
}

// ---------------------------------------------------------------
extern "C" void kernel_launch(void* const* d_in, const int* in_sizes, int n_in,
                              void* d_out, int out_size) {
    const float* x      = (const float*)d_in[0];
    const float* w_p    = (const float*)d_in[1];
    const float* b_p    = (const float*)d_in[2];
    const float* w_m    = (const float*)d_in[3];
    const float* b_m    = (const float*)d_in[4];
    const float* w_conv = (const float*)d_in[5];
    float* out = (float*)d_out;

    cudaFuncSetAttribute(k_convA,  cudaFuncAttributeMaxDynamicSharedMemorySize, CA_SMEM);
    cudaFuncSetAttribute(k_deform, cudaFuncAttributeMaxDynamicSharedMemorySize, SMEM_TOTAL);

    k_transpose_x<<<dim3(4, 4, Bn * Hh), dim3(32, 8)>>>(x);

    int wthreads = 9 * 128 * 128 + 9 * 27 * 128;
    k_transpose_w<<<(wthreads + 255) / 256, 256>>>(w_conv, w_p, w_m);

    // convA: tile 16(h) x 16(w): grid (W/16, H/16, B) = 128 CTAs (one wave)
    k_convA<<<dim3(8, 8, Bn), 512, CA_SMEM>>>(b_p, b_m);

    // deform: tile 4(h) x 16(w): grid (W/16, H/4, B)
    k_deform<<<dim3(8, 32, Bn), 512, SMEM_TOTAL>>>(out);
}